// round 1
// baseline (speedup 1.0000x reference)
#include <cuda_runtime.h>
#include <cstdint>

#define BATCH 2
#define C 256
#define NPOS 4096          // t*h*w = 4*32*32
#define NGROUP 32
#define CPG 8              // channels per group
#define CN ((size_t)C * NPOS)

// ---------------- scratch (static device globals; no allocations) ------------
__device__ float g_h[BATCH * C * NPOS];                       // 8 MB  groupnorm out
__device__ float g_q[BATCH * C * NPOS];                       // 8 MB
__device__ float g_k[BATCH * C * NPOS];                       // 8 MB
__device__ float g_v[BATCH * C * NPOS];                       // 8 MB
__device__ float g_a[BATCH * C * NPOS];                       // 8 MB  attn output
__device__ float g_s[(size_t)BATCH * NPOS * NPOS];            // 134 MB attn matrix

// ---------------- GroupNorm -------------------------------------------------
__global__ void __launch_bounds__(256) gn_kernel(const float* __restrict__ x,
                                                 const float* __restrict__ gamma,
                                                 const float* __restrict__ beta) {
    int b = blockIdx.x >> 5;
    int g = blockIdx.x & 31;
    const size_t base = ((size_t)b * C + g * CPG) * NPOS;
    const float4* xp = (const float4*)(x + base);
    float4* hp = (float4*)(g_h + base);
    const int NV = CPG * NPOS / 4;   // 8192 float4s

    float s = 0.f, ss = 0.f;
    for (int i = threadIdx.x; i < NV; i += 256) {
        float4 v = xp[i];
        s  += v.x + v.y + v.z + v.w;
        ss += v.x * v.x + v.y * v.y + v.z * v.z + v.w * v.w;
    }
    // block reduce (8 warps)
    #pragma unroll
    for (int o = 16; o; o >>= 1) {
        s  += __shfl_xor_sync(0xffffffffu, s, o);
        ss += __shfl_xor_sync(0xffffffffu, ss, o);
    }
    __shared__ float shs[8], shss[8];
    int w = threadIdx.x >> 5;
    if ((threadIdx.x & 31) == 0) { shs[w] = s; shss[w] = ss; }
    __syncthreads();
    float ts = 0.f, tss = 0.f;
    #pragma unroll
    for (int i = 0; i < 8; ++i) { ts += shs[i]; tss += shss[i]; }
    const float invN = 1.f / (CPG * NPOS);
    float mean = ts * invN;
    float var  = tss * invN - mean * mean;
    float inv  = rsqrtf(var + 1e-6f);

    for (int i = threadIdx.x; i < NV; i += 256) {
        int ch = g * CPG + (i >> 10);           // i*4 / 4096
        float gmul = gamma[ch] * inv;
        float gadd = beta[ch] - mean * gmul;
        float4 v = xp[i];
        v.x = v.x * gmul + gadd;
        v.y = v.y * gmul + gadd;
        v.z = v.z * gmul + gadd;
        v.w = v.w * gmul + gadd;
        hp[i] = v;
    }
}

// ---------------- tiled GEMM core: 128x128x16, 256 threads, 8x8/thread ------
// TA: A is row-major (M,K) -> transpose on smem store.  else A is (K,M), ld over m.
// TB: B is row-major (N,K) -> transpose on smem store.  else B is (K,N), ld over n.
template <bool TA, bool TB>
__device__ __forceinline__ void gemm_core(const float* __restrict__ A, int lda,
                                          const float* __restrict__ Bp, int ldb,
                                          int K, float acc[8][8]) {
    __shared__ __align__(16) float As[16][132];
    __shared__ __align__(16) float Bs[16][132];
    const int m0 = blockIdx.y * 128;
    const int n0 = blockIdx.x * 128;
    const int tid = threadIdx.x;
    const int tm8 = (tid >> 4) << 3;
    const int tn8 = (tid & 15) << 3;

    for (int k0 = 0; k0 < K; k0 += 16) {
        #pragma unroll
        for (int j = 0; j < 2; ++j) {
            int t = tid + j * 256;
            if (TA) {
                int row = t >> 2, kq = (t & 3) << 2;
                float4 v = *(const float4*)(A + (size_t)(m0 + row) * lda + k0 + kq);
                As[kq + 0][row] = v.x; As[kq + 1][row] = v.y;
                As[kq + 2][row] = v.z; As[kq + 3][row] = v.w;
            } else {
                int kr = t >> 5, mq = (t & 31) << 2;
                *(float4*)&As[kr][mq] =
                    *(const float4*)(A + (size_t)(k0 + kr) * lda + m0 + mq);
            }
            if (TB) {
                int row = t >> 2, kq = (t & 3) << 2;
                float4 v = *(const float4*)(Bp + (size_t)(n0 + row) * ldb + k0 + kq);
                Bs[kq + 0][row] = v.x; Bs[kq + 1][row] = v.y;
                Bs[kq + 2][row] = v.z; Bs[kq + 3][row] = v.w;
            } else {
                int kr = t >> 5, nq = (t & 31) << 2;
                *(float4*)&Bs[kr][nq] =
                    *(const float4*)(Bp + (size_t)(k0 + kr) * ldb + n0 + nq);
            }
        }
        __syncthreads();
        #pragma unroll
        for (int kk = 0; kk < 16; ++kk) {
            float rA[8], rB[8];
            *(float4*)(rA)     = *(const float4*)&As[kk][tm8];
            *(float4*)(rA + 4) = *(const float4*)&As[kk][tm8 + 4];
            *(float4*)(rB)     = *(const float4*)&Bs[kk][tn8];
            *(float4*)(rB + 4) = *(const float4*)&Bs[kk][tn8 + 4];
            #pragma unroll
            for (int i = 0; i < 8; ++i)
                #pragma unroll
                for (int jj = 0; jj < 8; ++jj)
                    acc[i][jj] = fmaf(rA[i], rB[jj], acc[i][jj]);
        }
        __syncthreads();
    }
}

// ---------------- QKV: Y = W @ H + b  (grid.z: b + 2*which) -----------------
__global__ void __launch_bounds__(256) qkv_kernel(
    const float* __restrict__ wq, const float* __restrict__ bq,
    const float* __restrict__ wk, const float* __restrict__ bk,
    const float* __restrict__ wv, const float* __restrict__ bv) {
    int z = blockIdx.z;
    int b = z & 1;
    int which = z >> 1;
    const float* W    = which == 0 ? wq : (which == 1 ? wk : wv);
    const float* bias = which == 0 ? bq : (which == 1 ? bk : bv);
    float* Y = (which == 0 ? g_q : (which == 1 ? g_k : g_v)) + (size_t)b * CN;
    const float* X = g_h + (size_t)b * CN;

    float acc[8][8];
    #pragma unroll
    for (int i = 0; i < 8; ++i)
        #pragma unroll
        for (int j = 0; j < 8; ++j) acc[i][j] = 0.f;

    gemm_core<true, false>(W, C, X, NPOS, C, acc);

    const int m0 = blockIdx.y * 128, n0 = blockIdx.x * 128;
    const int tm8 = (threadIdx.x >> 4) << 3, tn8 = (threadIdx.x & 15) << 3;
    #pragma unroll
    for (int i = 0; i < 8; ++i) {
        int m = m0 + tm8 + i;
        float bb = bias[m];
        float4 o0 = make_float4(acc[i][0] + bb, acc[i][1] + bb, acc[i][2] + bb, acc[i][3] + bb);
        float4 o1 = make_float4(acc[i][4] + bb, acc[i][5] + bb, acc[i][6] + bb, acc[i][7] + bb);
        float* yp = Y + (size_t)m * NPOS + n0 + tn8;
        *(float4*)(yp)     = o0;
        *(float4*)(yp + 4) = o1;
    }
}

// ---------------- S = scale * Q^T K  (per batch) -----------------------------
__global__ void __launch_bounds__(256) s_kernel() {
    int b = blockIdx.z;
    const float* Q  = g_q + (size_t)b * CN;
    const float* Kp = g_k + (size_t)b * CN;
    float* S = g_s + ((size_t)b << 24);

    float acc[8][8];
    #pragma unroll
    for (int i = 0; i < 8; ++i)
        #pragma unroll
        for (int j = 0; j < 8; ++j) acc[i][j] = 0.f;

    gemm_core<false, false>(Q, NPOS, Kp, NPOS, C, acc);

    const int m0 = blockIdx.y * 128, n0 = blockIdx.x * 128;
    const int tm8 = (threadIdx.x >> 4) << 3, tn8 = (threadIdx.x & 15) << 3;
    const float scale = 0.0625f;   // 256^-0.5
    #pragma unroll
    for (int i = 0; i < 8; ++i) {
        int m = m0 + tm8 + i;
        float4 o0 = make_float4(acc[i][0] * scale, acc[i][1] * scale,
                                acc[i][2] * scale, acc[i][3] * scale);
        float4 o1 = make_float4(acc[i][4] * scale, acc[i][5] * scale,
                                acc[i][6] * scale, acc[i][7] * scale);
        float* sp = S + (size_t)m * NPOS + n0 + tn8;
        *(float4*)(sp)     = o0;
        *(float4*)(sp + 4) = o1;
    }
}

// ---------------- softmax over rows of S (register-resident) -----------------
__global__ void __launch_bounds__(256) softmax_kernel() {
    size_t row = blockIdx.x;                 // b*4096 + i  -> contiguous row
    float* p = g_s + row * NPOS;
    const int tid = threadIdx.x;

    float4 r[4];
    #pragma unroll
    for (int c = 0; c < 4; ++c)
        r[c] = *(const float4*)(p + ((size_t)(tid + c * 256)) * 4);

    float m = -1e30f;
    #pragma unroll
    for (int c = 0; c < 4; ++c) {
        m = fmaxf(m, fmaxf(fmaxf(r[c].x, r[c].y), fmaxf(r[c].z, r[c].w)));
    }
    #pragma unroll
    for (int o = 16; o; o >>= 1) m = fmaxf(m, __shfl_xor_sync(0xffffffffu, m, o));
    __shared__ float shm[8], shsum[8];
    int w = tid >> 5;
    if ((tid & 31) == 0) shm[w] = m;
    __syncthreads();
    float mm = -1e30f;
    #pragma unroll
    for (int i = 0; i < 8; ++i) mm = fmaxf(mm, shm[i]);

    float s = 0.f;
    #pragma unroll
    for (int c = 0; c < 4; ++c) {
        r[c].x = expf(r[c].x - mm); r[c].y = expf(r[c].y - mm);
        r[c].z = expf(r[c].z - mm); r[c].w = expf(r[c].w - mm);
        s += r[c].x + r[c].y + r[c].z + r[c].w;
    }
    #pragma unroll
    for (int o = 16; o; o >>= 1) s += __shfl_xor_sync(0xffffffffu, s, o);
    if ((tid & 31) == 0) shsum[w] = s;
    __syncthreads();
    float ts = 0.f;
    #pragma unroll
    for (int i = 0; i < 8; ++i) ts += shsum[i];
    float inv = 1.f / ts;

    #pragma unroll
    for (int c = 0; c < 4; ++c) {
        r[c].x *= inv; r[c].y *= inv; r[c].z *= inv; r[c].w *= inv;
        *(float4*)(p + ((size_t)(tid + c * 256)) * 4) = r[c];
    }
}

// ---------------- A = V @ P^T  (NT gemm, per batch) --------------------------
__global__ void __launch_bounds__(256) av_kernel() {
    int b = blockIdx.z;
    const float* V = g_v + (size_t)b * CN;
    const float* P = g_s + ((size_t)b << 24);
    float* A = g_a + (size_t)b * CN;

    float acc[8][8];
    #pragma unroll
    for (int i = 0; i < 8; ++i)
        #pragma unroll
        for (int j = 0; j < 8; ++j) acc[i][j] = 0.f;

    gemm_core<true, true>(V, NPOS, P, NPOS, NPOS, acc);

    const int m0 = blockIdx.y * 128, n0 = blockIdx.x * 128;
    const int tm8 = (threadIdx.x >> 4) << 3, tn8 = (threadIdx.x & 15) << 3;
    #pragma unroll
    for (int i = 0; i < 8; ++i) {
        int m = m0 + tm8 + i;
        float* ap = A + (size_t)m * NPOS + n0 + tn8;
        *(float4*)(ap)     = make_float4(acc[i][0], acc[i][1], acc[i][2], acc[i][3]);
        *(float4*)(ap + 4) = make_float4(acc[i][4], acc[i][5], acc[i][6], acc[i][7]);
    }
}

// ---------------- out = x + Wp @ A + bp --------------------------------------
__global__ void __launch_bounds__(256) proj_kernel(const float* __restrict__ wp,
                                                   const float* __restrict__ bp,
                                                   const float* __restrict__ x,
                                                   float* __restrict__ out) {
    int b = blockIdx.z;
    const float* X = g_a + (size_t)b * CN;

    float acc[8][8];
    #pragma unroll
    for (int i = 0; i < 8; ++i)
        #pragma unroll
        for (int j = 0; j < 8; ++j) acc[i][j] = 0.f;

    gemm_core<true, false>(wp, C, X, NPOS, C, acc);

    const int m0 = blockIdx.y * 128, n0 = blockIdx.x * 128;
    const int tm8 = (threadIdx.x >> 4) << 3, tn8 = (threadIdx.x & 15) << 3;
    #pragma unroll
    for (int i = 0; i < 8; ++i) {
        int m = m0 + tm8 + i;
        float bb = bp[m];
        size_t off = (size_t)b * CN + (size_t)m * NPOS + n0 + tn8;
        float4 x0 = *(const float4*)(x + off);
        float4 x1 = *(const float4*)(x + off + 4);
        float4 o0 = make_float4(x0.x + acc[i][0] + bb, x0.y + acc[i][1] + bb,
                                x0.z + acc[i][2] + bb, x0.w + acc[i][3] + bb);
        float4 o1 = make_float4(x1.x + acc[i][4] + bb, x1.y + acc[i][5] + bb,
                                x1.z + acc[i][6] + bb, x1.w + acc[i][7] + bb);
        *(float4*)(out + off)     = o0;
        *(float4*)(out + off + 4) = o1;
    }
}

// ---------------- launch ------------------------------------------------------
extern "C" void kernel_launch(void* const* d_in, const int* in_sizes, int n_in,
                              void* d_out, int out_size) {
    const float* x  = (const float*)d_in[0];
    const float* gs = (const float*)d_in[1];
    const float* gb = (const float*)d_in[2];
    const float* wq = (const float*)d_in[3];
    const float* bq = (const float*)d_in[4];
    const float* wk = (const float*)d_in[5];
    const float* bk = (const float*)d_in[6];
    const float* wv = (const float*)d_in[7];
    const float* bv = (const float*)d_in[8];
    const float* wp = (const float*)d_in[9];
    const float* bp = (const float*)d_in[10];
    float* out = (float*)d_out;

    gn_kernel<<<BATCH * NGROUP, 256>>>(x, gs, gb);
    qkv_kernel<<<dim3(NPOS / 128, C / 128, 3 * BATCH), 256>>>(wq, bq, wk, bk, wv, bv);
    s_kernel<<<dim3(NPOS / 128, NPOS / 128, BATCH), 256>>>();
    softmax_kernel<<<BATCH * NPOS, 256>>>();
    av_kernel<<<dim3(NPOS / 128, C / 128, BATCH), 256>>>();
    proj_kernel<<<dim3(NPOS / 128, C / 128, BATCH), 256>>>(wp, bp, x, out);
}

// round 3
// speedup vs baseline: 2.0725x; 2.0725x over previous
#include <cuda_runtime.h>
#include <cuda_bf16.h>
#include <cstdint>

using bf16 = __nv_bfloat16;

#define BATCH 2
#define C 256
#define NPOS 4096
#define CN ((size_t)C * NPOS)
#define SN ((size_t)NPOS * NPOS)

// ---------------- scratch (static device globals) ---------------------------
__device__ __align__(16) bf16 g_h_hi[BATCH * NPOS * C];
__device__ __align__(16) bf16 g_h_lo[BATCH * NPOS * C];
__device__ __align__(16) bf16 g_w_hi[4 * C * C];
__device__ __align__(16) bf16 g_w_lo[4 * C * C];
__device__ __align__(16) bf16 g_q_hi[BATCH * NPOS * C];
__device__ __align__(16) bf16 g_q_lo[BATCH * NPOS * C];
__device__ __align__(16) bf16 g_k_hi[BATCH * NPOS * C];
__device__ __align__(16) bf16 g_k_lo[BATCH * NPOS * C];
__device__ __align__(16) bf16 g_v_hi[BATCH * C * NPOS];   // channel-major
__device__ __align__(16) bf16 g_v_lo[BATCH * C * NPOS];
__device__ __align__(16) float g_s[BATCH * NPOS * NPOS];  // 134 MB
__device__ __align__(16) bf16 g_p_hi[BATCH * NPOS * NPOS];
__device__ __align__(16) bf16 g_p_lo[BATCH * NPOS * NPOS];
__device__ __align__(16) bf16 g_o_hi[BATCH * NPOS * C];   // position-major
__device__ __align__(16) bf16 g_o_lo[BATCH * NPOS * C];
__device__ float g_stats[BATCH * 32 * 2];

// ---------------- PTX primitives ---------------------------------------------
__device__ __forceinline__ uint32_t smem_u32(const void* p) {
    uint32_t r;
    asm("{ .reg .u64 t; cvta.to.shared.u64 t, %1; cvt.u32.u64 %0, t; }" : "=r"(r) : "l"(p));
    return r;
}

__device__ __forceinline__ void cpasync16(uint32_t s, const void* g) {
    asm volatile("cp.async.cg.shared.global [%0], [%1], 16;" :: "r"(s), "l"(g) : "memory");
}
__device__ __forceinline__ void cp_commit() {
    asm volatile("cp.async.commit_group;" ::: "memory");
}
__device__ __forceinline__ void cp_wait1() {
    asm volatile("cp.async.wait_group 1;" ::: "memory");
}
__device__ __forceinline__ void cp_wait0() {
    asm volatile("cp.async.wait_group 0;" ::: "memory");
}

__device__ __forceinline__ void ldsm4(uint32_t (&r)[4], uint32_t addr) {
    asm volatile("ldmatrix.sync.aligned.m8n8.x4.shared.b16 {%0,%1,%2,%3}, [%4];"
                 : "=r"(r[0]), "=r"(r[1]), "=r"(r[2]), "=r"(r[3]) : "r"(addr));
}

__device__ __forceinline__ void mma16816(float (&c)[4], const uint32_t (&a)[4],
                                         uint32_t b0, uint32_t b1) {
    asm volatile(
        "mma.sync.aligned.m16n8k16.row.col.f32.bf16.bf16.f32 "
        "{%0,%1,%2,%3}, {%4,%5,%6,%7}, {%8,%9}, {%0,%1,%2,%3};"
        : "+f"(c[0]), "+f"(c[1]), "+f"(c[2]), "+f"(c[3])
        : "r"(a[0]), "r"(a[1]), "r"(a[2]), "r"(a[3]), "r"(b0), "r"(b1));
}

// ---------------- GEMM core ---------------------------------------------------
// Tile 128x128, 256 threads, K-chunk 32, double-buffered cp.async.
// A: [128][K] row-major (K-major). B: [128][K] row-major. D = A * B^T (+split).
// smem per stage: Ah, Al, Bh, Bl each 128 rows x 32 bf16 padded to 40 (80 B/row).
#define ROWB 80
#define SM_AH 0
#define SM_AL 10240
#define SM_BH 20480
#define SM_BL 30720
#define STAGE 40960
#define SMEM_BYTES (2 * STAGE)

__device__ __forceinline__ void issue_tile(uint32_t sbase, const bf16* g, int ld) {
    int t = threadIdx.x;
    #pragma unroll
    for (int i = 0; i < 2; ++i) {
        int v = t + (i << 8);
        int row = v >> 2, c8 = (v & 3) << 3;
        cpasync16(sbase + row * ROWB + c8 * 2, g + (size_t)row * ld + c8);
    }
}

__device__ __forceinline__ void issue_chunk(uint32_t sb,
        const bf16* ah, const bf16* al, int lda,
        const bf16* bh, const bf16* bl, int ldb, int k0) {
    issue_tile(sb + SM_AH, ah + k0, lda);
    issue_tile(sb + SM_AL, al + k0, lda);
    issue_tile(sb + SM_BH, bh + k0, ldb);
    issue_tile(sb + SM_BL, bl + k0, ldb);
}

__device__ __forceinline__ void compute_chunk(uint32_t s, float acc[4][4][4]) {
    const int lane = threadIdx.x & 31, wid = threadIdx.x >> 5;
    const int m0w = (wid & 1) << 6;      // 0 or 64
    const int n0w = (wid >> 1) << 5;     // 0,32,64,96
    const int arow = lane & 15;
    const int khalf = (lane >> 4) << 3;  // 0 or 8
    #pragma unroll
    for (int s16 = 0; s16 < 32; s16 += 16) {
        const int coff = (s16 + khalf) * 2;
        uint32_t a_h[4][4], a_l[4][4], b_h[2][4], b_l[2][4];
        #pragma unroll
        for (int mi = 0; mi < 4; ++mi) {
            uint32_t r = (m0w + mi * 16 + arow) * ROWB + coff;
            ldsm4(a_h[mi], s + SM_AH + r);
            ldsm4(a_l[mi], s + SM_AL + r);
        }
        #pragma unroll
        for (int nj = 0; nj < 2; ++nj) {
            uint32_t r = (n0w + nj * 16 + arow) * ROWB + coff;
            ldsm4(b_h[nj], s + SM_BH + r);
            ldsm4(b_l[nj], s + SM_BL + r);
        }
        #pragma unroll
        for (int mi = 0; mi < 4; ++mi)
            #pragma unroll
            for (int ni = 0; ni < 4; ++ni) {
                const int nj = ni >> 1, sel = ni & 1;
                mma16816(acc[mi][ni], a_h[mi], b_h[nj][sel], b_h[nj][sel + 2]);
                mma16816(acc[mi][ni], a_h[mi], b_l[nj][sel], b_l[nj][sel + 2]);
                mma16816(acc[mi][ni], a_l[mi], b_h[nj][sel], b_h[nj][sel + 2]);
            }
    }
}

__device__ __forceinline__ void gemm_run(uint32_t sb,
        const bf16* ah, const bf16* al, int lda,
        const bf16* bh, const bf16* bl, int ldb,
        int K, float acc[4][4][4]) {
    #pragma unroll
    for (int mi = 0; mi < 4; ++mi)
        #pragma unroll
        for (int ni = 0; ni < 4; ++ni)
            #pragma unroll
            for (int r = 0; r < 4; ++r) acc[mi][ni][r] = 0.f;

    const int nc = K >> 5;
    issue_chunk(sb, ah, al, lda, bh, bl, ldb, 0);
    cp_commit();
    for (int c = 0; c < nc; ++c) {
        uint32_t s = sb + (c & 1) * STAGE;
        if (c + 1 < nc) {
            issue_chunk(sb + ((c + 1) & 1) * STAGE, ah, al, lda, bh, bl, ldb, (c + 1) << 5);
            cp_commit();
            cp_wait1();
        } else {
            cp_wait0();
        }
        __syncthreads();
        compute_chunk(s, acc);
        __syncthreads();
    }
}

// epilogue coordinate helpers
#define EPI_COORDS                                     \
    const int lane = threadIdx.x & 31;                 \
    const int wid = threadIdx.x >> 5;                  \
    const int mw = (wid & 1) << 6;                     \
    const int nw = (wid >> 1) << 5;                    \
    const int r0 = lane >> 2;                          \
    const int c0 = (lane & 3) << 1;

__device__ __forceinline__ void store_pair_split(bf16* hi, bf16* lo, size_t off,
                                                 float v0, float v1) {
    bf16 h0 = __float2bfloat16(v0), h1 = __float2bfloat16(v1);
    __nv_bfloat162 ph; ph.x = h0; ph.y = h1;
    __nv_bfloat162 pl;
    pl.x = __float2bfloat16(v0 - __bfloat162float(h0));
    pl.y = __float2bfloat16(v1 - __bfloat162float(h1));
    *reinterpret_cast<__nv_bfloat162*>(hi + off) = ph;
    *reinterpret_cast<__nv_bfloat162*>(lo + off) = pl;
}

// ---------------- prep kernels ------------------------------------------------
__global__ void __launch_bounds__(256) conv_w_kernel(
        const float* __restrict__ wq, const float* __restrict__ wk,
        const float* __restrict__ wv, const float* __restrict__ wp) {
    int i = blockIdx.x * 256 + threadIdx.x;
    int which = i >> 16, j = i & 65535;
    const float* w = which == 0 ? wq : (which == 1 ? wk : (which == 2 ? wv : wp));
    float v = w[j];
    bf16 h = __float2bfloat16(v);
    g_w_hi[i] = h;
    g_w_lo[i] = __float2bfloat16(v - __bfloat162float(h));
}

__global__ void __launch_bounds__(256) gn_stats_kernel(const float* __restrict__ x) {
    int b = blockIdx.x >> 5, g = blockIdx.x & 31;
    const size_t base = ((size_t)b * C + g * 8) * NPOS;
    const float4* xp = (const float4*)(x + base);
    const int NV = 8 * NPOS / 4;
    float s = 0.f, ss = 0.f;
    for (int i = threadIdx.x; i < NV; i += 256) {
        float4 v = xp[i];
        s  += v.x + v.y + v.z + v.w;
        ss += v.x * v.x + v.y * v.y + v.z * v.z + v.w * v.w;
    }
    #pragma unroll
    for (int o = 16; o; o >>= 1) {
        s  += __shfl_xor_sync(0xffffffffu, s, o);
        ss += __shfl_xor_sync(0xffffffffu, ss, o);
    }
    __shared__ float shs[8], shss[8];
    int w = threadIdx.x >> 5;
    if ((threadIdx.x & 31) == 0) { shs[w] = s; shss[w] = ss; }
    __syncthreads();
    if (threadIdx.x == 0) {
        float ts = 0.f, tss = 0.f;
        #pragma unroll
        for (int i = 0; i < 8; ++i) { ts += shs[i]; tss += shss[i]; }
        const float invN = 1.f / (8 * NPOS);
        float mean = ts * invN;
        float var = tss * invN - mean * mean;
        g_stats[blockIdx.x * 2]     = mean;
        g_stats[blockIdx.x * 2 + 1] = rsqrtf(var + 1e-6f);
    }
}

__global__ void gn_apply_kernel(const float* __restrict__ x,
                                const float* __restrict__ gamma,
                                const float* __restrict__ beta) {
    __shared__ float tile[32][33];
    int b = blockIdx.z, c0b = blockIdx.y * 32, n0b = blockIdx.x * 32;
    int tx = threadIdx.x, ty = threadIdx.y;
    #pragma unroll
    for (int i = 0; i < 4; ++i) {
        int cl = ty + i * 8;
        int c = c0b + cl;
        int g = c >> 3;
        float mean = g_stats[(b * 32 + g) * 2];
        float inv  = g_stats[(b * 32 + g) * 2 + 1];
        float gmul = gamma[c] * inv;
        float gadd = beta[c] - mean * gmul;
        float v = x[((size_t)b * C + c) * NPOS + n0b + tx];
        tile[cl][tx] = v * gmul + gadd;
    }
    __syncthreads();
    #pragma unroll
    for (int i = 0; i < 4; ++i) {
        int nl = ty + i * 8;
        float v = tile[tx][nl];
        bf16 h = __float2bfloat16(v);
        size_t o = ((size_t)b * NPOS + n0b + nl) * C + c0b + tx;
        g_h_hi[o] = h;
        g_h_lo[o] = __float2bfloat16(v - __bfloat162float(h));
    }
}

// ---------------- GEMM kernels -----------------------------------------------
// Q/K: out[pos, cout] = H[pos,:] . W[cout,:]^T + bias
__global__ void __launch_bounds__(256) qk_gemm(const float* __restrict__ bq,
                                               const float* __restrict__ bk) {
    extern __shared__ char smem[];
    uint32_t sb = smem_u32(smem);
    int b = blockIdx.z >> 1, which = blockIdx.z & 1;
    int m0 = blockIdx.y * 128, n0 = blockIdx.x * 128;
    size_t ab = ((size_t)b * NPOS + m0) * C;
    size_t wb = (size_t)which * C * C + (size_t)n0 * C;
    float acc[4][4][4];
    gemm_run(sb, g_h_hi + ab, g_h_lo + ab, C, g_w_hi + wb, g_w_lo + wb, C, C, acc);

    const float* bias = which == 0 ? bq : bk;
    bf16* hi = which == 0 ? g_q_hi : g_k_hi;
    bf16* lo = which == 0 ? g_q_lo : g_k_lo;
    EPI_COORDS;
    #pragma unroll
    for (int ni = 0; ni < 4; ++ni) {
        int colg = n0 + nw + ni * 8 + c0;
        float bb0 = bias[colg], bb1 = bias[colg + 1];
        #pragma unroll
        for (int mi = 0; mi < 4; ++mi)
            #pragma unroll
            for (int rr = 0; rr < 2; ++rr) {
                int rowg = m0 + mw + mi * 16 + r0 + rr * 8;
                size_t off = ((size_t)b * NPOS + rowg) * C + colg;
                store_pair_split(hi, lo, off,
                                 acc[mi][ni][rr * 2] + bb0, acc[mi][ni][rr * 2 + 1] + bb1);
            }
    }
}

// V: out[c, pos] = Wv[c,:] . H[pos,:]^T + bv[c]   (channel-major)
__global__ void __launch_bounds__(256) v_gemm(const float* __restrict__ bv) {
    extern __shared__ char smem[];
    uint32_t sb = smem_u32(smem);
    int b = blockIdx.z;
    int m0 = blockIdx.y * 128, n0 = blockIdx.x * 128;
    size_t wb = (size_t)2 * C * C + (size_t)m0 * C;
    size_t hb = ((size_t)b * NPOS + n0) * C;
    float acc[4][4][4];
    gemm_run(sb, g_w_hi + wb, g_w_lo + wb, C, g_h_hi + hb, g_h_lo + hb, C, C, acc);

    EPI_COORDS;
    #pragma unroll
    for (int mi = 0; mi < 4; ++mi)
        #pragma unroll
        for (int rr = 0; rr < 2; ++rr) {
            int rowg = m0 + mw + mi * 16 + r0 + rr * 8;
            float bb = bv[rowg];
            #pragma unroll
            for (int ni = 0; ni < 4; ++ni) {
                int colg = n0 + nw + ni * 8 + c0;
                size_t off = (size_t)b * CN + (size_t)rowg * NPOS + colg;
                store_pair_split(g_v_hi, g_v_lo, off,
                                 acc[mi][ni][rr * 2] + bb, acc[mi][ni][rr * 2 + 1] + bb);
            }
        }
}

// S: [i,j] = 1/16 * Q[i,:] . K[j,:]^T
__global__ void __launch_bounds__(256) s_gemm() {
    extern __shared__ char smem[];
    uint32_t sb = smem_u32(smem);
    int b = blockIdx.z;
    int m0 = blockIdx.y * 128, n0 = blockIdx.x * 128;
    size_t qb = ((size_t)b * NPOS + m0) * C;
    size_t kb = ((size_t)b * NPOS + n0) * C;
    float acc[4][4][4];
    gemm_run(sb, g_q_hi + qb, g_q_lo + qb, C, g_k_hi + kb, g_k_lo + kb, C, C, acc);

    EPI_COORDS;
    float* S = g_s + (size_t)b * SN;
    #pragma unroll
    for (int mi = 0; mi < 4; ++mi)
        #pragma unroll
        for (int rr = 0; rr < 2; ++rr) {
            int rowg = m0 + mw + mi * 16 + r0 + rr * 8;
            #pragma unroll
            for (int ni = 0; ni < 4; ++ni) {
                int colg = n0 + nw + ni * 8 + c0;
                float2 v = make_float2(acc[mi][ni][rr * 2] * 0.0625f,
                                       acc[mi][ni][rr * 2 + 1] * 0.0625f);
                *reinterpret_cast<float2*>(S + (size_t)rowg * NPOS + colg) = v;
            }
        }
}

// softmax rows of S -> P (bf16 hi/lo)
__global__ void __launch_bounds__(256) softmax_kernel() {
    size_t row = blockIdx.x;
    const float* p = g_s + row * NPOS;
    bf16* ph = g_p_hi + row * NPOS;
    bf16* pl = g_p_lo + row * NPOS;
    const int tid = threadIdx.x;

    float4 r[4];
    #pragma unroll
    for (int c = 0; c < 4; ++c)
        r[c] = *(const float4*)(p + ((size_t)(tid + c * 256)) * 4);

    float m = -1e30f;
    #pragma unroll
    for (int c = 0; c < 4; ++c)
        m = fmaxf(m, fmaxf(fmaxf(r[c].x, r[c].y), fmaxf(r[c].z, r[c].w)));
    #pragma unroll
    for (int o = 16; o; o >>= 1) m = fmaxf(m, __shfl_xor_sync(0xffffffffu, m, o));
    __shared__ float shm[8], shsum[8];
    int w = tid >> 5;
    if ((tid & 31) == 0) shm[w] = m;
    __syncthreads();
    float mm = -1e30f;
    #pragma unroll
    for (int i = 0; i < 8; ++i) mm = fmaxf(mm, shm[i]);

    float s = 0.f;
    #pragma unroll
    for (int c = 0; c < 4; ++c) {
        r[c].x = expf(r[c].x - mm); r[c].y = expf(r[c].y - mm);
        r[c].z = expf(r[c].z - mm); r[c].w = expf(r[c].w - mm);
        s += r[c].x + r[c].y + r[c].z + r[c].w;
    }
    #pragma unroll
    for (int o = 16; o; o >>= 1) s += __shfl_xor_sync(0xffffffffu, s, o);
    if ((tid & 31) == 0) shsum[w] = s;
    __syncthreads();
    float ts = 0.f;
    #pragma unroll
    for (int i = 0; i < 8; ++i) ts += shsum[i];
    float inv = 1.f / ts;

    #pragma unroll
    for (int c = 0; c < 4; ++c) {
        float f[4] = {r[c].x * inv, r[c].y * inv, r[c].z * inv, r[c].w * inv};
        __align__(8) bf16 h[4];
        __align__(8) bf16 l[4];
        #pragma unroll
        for (int j = 0; j < 4; ++j) {
            h[j] = __float2bfloat16(f[j]);
            l[j] = __float2bfloat16(f[j] - __bfloat162float(h[j]));
        }
        size_t o = ((size_t)(tid + c * 256)) * 4;
        *reinterpret_cast<uint2*>(ph + o) = *reinterpret_cast<const uint2*>(h);
        *reinterpret_cast<uint2*>(pl + o) = *reinterpret_cast<const uint2*>(l);
    }
}

// AV: O[i, c] = P[i,:] . Vc[c,:]^T   (K = 4096), O position-major
__global__ void __launch_bounds__(256) av_gemm() {
    extern __shared__ char smem[];
    uint32_t sb = smem_u32(smem);
    int b = blockIdx.z;
    int m0 = blockIdx.y * 128, n0 = blockIdx.x * 128;
    size_t pb = (size_t)b * SN + (size_t)m0 * NPOS;
    size_t vb = (size_t)b * CN + (size_t)n0 * NPOS;
    float acc[4][4][4];
    gemm_run(sb, g_p_hi + pb, g_p_lo + pb, NPOS, g_v_hi + vb, g_v_lo + vb, NPOS,
             NPOS, acc);

    EPI_COORDS;
    #pragma unroll
    for (int mi = 0; mi < 4; ++mi)
        #pragma unroll
        for (int rr = 0; rr < 2; ++rr) {
            int rowg = m0 + mw + mi * 16 + r0 + rr * 8;
            #pragma unroll
            for (int ni = 0; ni < 4; ++ni) {
                int colg = n0 + nw + ni * 8 + c0;
                size_t off = ((size_t)b * NPOS + rowg) * C + colg;
                store_pair_split(g_o_hi, g_o_lo, off,
                                 acc[mi][ni][rr * 2], acc[mi][ni][rr * 2 + 1]);
            }
        }
}

// proj: out[c, n] = x[c, n] + Wp[c,:] . O[n,:]^T + bp[c]
__global__ void __launch_bounds__(256) proj_gemm(const float* __restrict__ bp,
                                                 const float* __restrict__ x,
                                                 float* __restrict__ out) {
    extern __shared__ char smem[];
    uint32_t sb = smem_u32(smem);
    int b = blockIdx.z;
    int m0 = blockIdx.y * 128, n0 = blockIdx.x * 128;
    size_t wb = (size_t)3 * C * C + (size_t)m0 * C;
    size_t ob = ((size_t)b * NPOS + n0) * C;
    float acc[4][4][4];
    gemm_run(sb, g_w_hi + wb, g_w_lo + wb, C, g_o_hi + ob, g_o_lo + ob, C, C, acc);

    EPI_COORDS;
    #pragma unroll
    for (int mi = 0; mi < 4; ++mi)
        #pragma unroll
        for (int rr = 0; rr < 2; ++rr) {
            int rowg = m0 + mw + mi * 16 + r0 + rr * 8;
            float bb = bp[rowg];
            #pragma unroll
            for (int ni = 0; ni < 4; ++ni) {
                int colg = n0 + nw + ni * 8 + c0;
                size_t off = (size_t)b * CN + (size_t)rowg * NPOS + colg;
                float2 xv = *reinterpret_cast<const float2*>(x + off);
                float2 ov = make_float2(xv.x + acc[mi][ni][rr * 2] + bb,
                                        xv.y + acc[mi][ni][rr * 2 + 1] + bb);
                *reinterpret_cast<float2*>(out + off) = ov;
            }
        }
}

// ---------------- launch ------------------------------------------------------
extern "C" void kernel_launch(void* const* d_in, const int* in_sizes, int n_in,
                              void* d_out, int out_size) {
    const float* x  = (const float*)d_in[0];
    const float* gs = (const float*)d_in[1];
    const float* gb = (const float*)d_in[2];
    const float* wq = (const float*)d_in[3];
    const float* bq = (const float*)d_in[4];
    const float* wk = (const float*)d_in[5];
    const float* bk = (const float*)d_in[6];
    const float* wv = (const float*)d_in[7];
    const float* bv = (const float*)d_in[8];
    const float* wp = (const float*)d_in[9];
    const float* bp = (const float*)d_in[10];
    float* out = (float*)d_out;

    static bool attr_done = false;
    if (!attr_done) {
        cudaFuncSetAttribute(qk_gemm,   cudaFuncAttributeMaxDynamicSharedMemorySize, SMEM_BYTES);
        cudaFuncSetAttribute(v_gemm,    cudaFuncAttributeMaxDynamicSharedMemorySize, SMEM_BYTES);
        cudaFuncSetAttribute(s_gemm,    cudaFuncAttributeMaxDynamicSharedMemorySize, SMEM_BYTES);
        cudaFuncSetAttribute(av_gemm,   cudaFuncAttributeMaxDynamicSharedMemorySize, SMEM_BYTES);
        cudaFuncSetAttribute(proj_gemm, cudaFuncAttributeMaxDynamicSharedMemorySize, SMEM_BYTES);
        attr_done = true;
    }

    conv_w_kernel<<<4 * C * C / 256, 256>>>(wq, wk, wv, wp);
    gn_stats_kernel<<<BATCH * 32, 256>>>(x);
    gn_apply_kernel<<<dim3(NPOS / 32, C / 32, BATCH), dim3(32, 8)>>>(x, gs, gb);
    qk_gemm<<<dim3(C / 128, NPOS / 128, 2 * BATCH), 256, SMEM_BYTES>>>(bq, bk);
    v_gemm<<<dim3(NPOS / 128, C / 128, BATCH), 256, SMEM_BYTES>>>(bv);
    s_gemm<<<dim3(NPOS / 128, NPOS / 128, BATCH), 256, SMEM_BYTES>>>();
    softmax_kernel<<<BATCH * NPOS, 256>>>();
    av_gemm<<<dim3(C / 128, NPOS / 128, BATCH), 256, SMEM_BYTES>>>();
    proj_gemm<<<dim3(NPOS / 128, C / 128, BATCH), 256, SMEM_BYTES>>>(bp, x, out);
}

// round 5
// speedup vs baseline: 3.1462x; 1.5181x over previous
#include <cuda_runtime.h>
#include <cstdint>

#define BATCH 2
#define C 256
#define NPOS 4096
#define CN ((size_t)C * NPOS)
#define SN ((size_t)NPOS * NPOS)

// ---------------- scratch (static device globals) ---------------------------
__device__ __align__(16) float g_h[BATCH * NPOS * C];   // gn out, position-major, tf32-rounded
__device__ __align__(16) float g_w[4 * C * C];          // weights, tf32-rounded
__device__ __align__(16) float g_q[BATCH * NPOS * C];   // position-major
__device__ __align__(16) float g_k[BATCH * NPOS * C];
__device__ __align__(16) float g_v[BATCH * C * NPOS];   // channel-major
__device__ __align__(16) float g_s[BATCH * SN];         // S, then P in-place (134 MB)
__device__ __align__(16) float g_o[BATCH * NPOS * C];   // attn out, position-major
__device__ float g_stats[BATCH * 32 * 2];

// ---------------- PTX primitives ---------------------------------------------
__device__ __forceinline__ uint32_t smem_u32(const void* p) {
    uint32_t r;
    asm("{ .reg .u64 t; cvta.to.shared.u64 t, %1; cvt.u32.u64 %0, t; }" : "=r"(r) : "l"(p));
    return r;
}
__device__ __forceinline__ float tf32r(float x) {
    uint32_t u;
    asm("cvt.rna.tf32.f32 %0, %1;" : "=r"(u) : "f"(x));
    return __uint_as_float(u);
}
__device__ __forceinline__ void cpasync16(uint32_t s, const void* g) {
    asm volatile("cp.async.cg.shared.global [%0], [%1], 16;" :: "r"(s), "l"(g) : "memory");
}
__device__ __forceinline__ void cp_commit() {
    asm volatile("cp.async.commit_group;" ::: "memory");
}
__device__ __forceinline__ void cp_wait1() {
    asm volatile("cp.async.wait_group 1;" ::: "memory");
}
__device__ __forceinline__ void cp_wait0() {
    asm volatile("cp.async.wait_group 0;" ::: "memory");
}
__device__ __forceinline__ void ldsm4(uint32_t (&r)[4], uint32_t addr) {
    asm volatile("ldmatrix.sync.aligned.m8n8.x4.shared.b16 {%0,%1,%2,%3}, [%4];"
                 : "=r"(r[0]), "=r"(r[1]), "=r"(r[2]), "=r"(r[3]) : "r"(addr));
}
__device__ __forceinline__ void mma8(float (&c)[4], const uint32_t (&a)[4],
                                     uint32_t b0, uint32_t b1) {
    asm volatile(
        "mma.sync.aligned.m16n8k8.row.col.f32.tf32.tf32.f32 "
        "{%0,%1,%2,%3}, {%4,%5,%6,%7}, {%8,%9}, {%0,%1,%2,%3};"
        : "+f"(c[0]), "+f"(c[1]), "+f"(c[2]), "+f"(c[3])
        : "r"(a[0]), "r"(a[1]), "r"(a[2]), "r"(a[3]), "r"(b0), "r"(b1));
}

// ---------------- GEMM core ---------------------------------------------------
// CTA tile 128x128, 256 threads (8 warps, 2x4), warp tile 64x32, K-chunk 32 fp32.
// Operands: A [128 rows][K] fp32 K-major, B [128 rows][K] fp32 K-major. D = A*B^T.
// SMEM row stride 144 B (32 fp32 data + pad); 3-stage cp.async ring.
#define STRIDE 144
#define SM_B_OFF 18432
#define STAGE_SZ 36864
#define SMEM_BYTES (3 * STAGE_SZ)   // 110592

__device__ __forceinline__ void issue_chunk(uint32_t sb, const float* A, int lda,
                                            const float* B, int ldb, int k0) {
    const int t = threadIdx.x;
    #pragma unroll
    for (int i = 0; i < 4; ++i) {
        int v = t + (i << 8);
        int row = v >> 3, seg = v & 7;
        cpasync16(sb + row * STRIDE + seg * 16, A + (size_t)row * lda + k0 + seg * 4);
    }
    #pragma unroll
    for (int i = 0; i < 4; ++i) {
        int v = t + (i << 8);
        int row = v >> 3, seg = v & 7;
        cpasync16(sb + SM_B_OFF + row * STRIDE + seg * 16,
                  B + (size_t)row * ldb + k0 + seg * 4);
    }
}

__device__ __forceinline__ void compute_chunk(uint32_t s, float acc[4][4][4]) {
    const int lane = threadIdx.x & 31, wid = threadIdx.x >> 5;
    const int m0w = (wid & 1) << 6;      // 0 / 64
    const int n0w = (wid >> 1) << 5;     // 0,32,64,96
    // A ldmatrix thread map: rows 0-15 by (lane&15), byte-col 16 for lanes 16-31
    const int arow = lane & 15;
    const int acol = (lane & 16) ? 16 : 0;
    // B ldmatrix thread map: octets -> (rows 0-7 c0 | rows 0-7 c16 | rows 8-15 c0 | rows 8-15 c16)
    const int brow = (lane & 7) + ((lane & 16) >> 1);
    const int bcol = (lane & 8) ? 16 : 0;
    #pragma unroll
    for (int k8 = 0; k8 < 4; ++k8) {
        const int kb = k8 * 32;
        uint32_t a[4][4], b[2][4];
        #pragma unroll
        for (int mi = 0; mi < 4; ++mi)
            ldsm4(a[mi], s + (m0w + mi * 16 + arow) * STRIDE + acol + kb);
        #pragma unroll
        for (int nj = 0; nj < 2; ++nj)
            ldsm4(b[nj], s + SM_B_OFF + (n0w + nj * 16 + brow) * STRIDE + bcol + kb);
        #pragma unroll
        for (int mi = 0; mi < 4; ++mi)
            #pragma unroll
            for (int ni = 0; ni < 4; ++ni) {
                const int nj = ni >> 1, off = (ni & 1) * 2;
                mma8(acc[mi][ni], a[mi], b[nj][off], b[nj][off + 1]);
            }
    }
}

__device__ __forceinline__ void gemm_run(uint32_t sb, const float* A, int lda,
                                         const float* B, int ldb, int K,
                                         float acc[4][4][4]) {
    #pragma unroll
    for (int mi = 0; mi < 4; ++mi)
        #pragma unroll
        for (int ni = 0; ni < 4; ++ni)
            #pragma unroll
            for (int r = 0; r < 4; ++r) acc[mi][ni][r] = 0.f;

    const int nc = K >> 5;
    #pragma unroll
    for (int s = 0; s < 2; ++s) {
        issue_chunk(sb + s * STAGE_SZ, A, lda, B, ldb, s << 5);
        cp_commit();
    }
    for (int c = 0; c < nc; ++c) {
        if (c >= nc - 2) cp_wait0(); else cp_wait1();
        __syncthreads();
        if (c + 2 < nc) {
            int slot = (c + 2) % 3;
            issue_chunk(sb + slot * STAGE_SZ, A, lda, B, ldb, (c + 2) << 5);
            cp_commit();
        }
        compute_chunk(sb + (c % 3) * STAGE_SZ, acc);
    }
}

// epilogue coordinates (C fragment m16n8: rows lane>>2 (+8), cols (lane&3)*2 (+1))
#define EPI_COORDS                                     \
    const int lane = threadIdx.x & 31;                 \
    const int wid = threadIdx.x >> 5;                  \
    const int mw = (wid & 1) << 6;                     \
    const int nw = (wid >> 1) << 5;                    \
    const int r0 = lane >> 2;                          \
    const int c0 = (lane & 3) << 1;

// ---------------- prep kernels ------------------------------------------------
__global__ void __launch_bounds__(256) conv_w_kernel(
        const float* __restrict__ wq, const float* __restrict__ wk,
        const float* __restrict__ wv, const float* __restrict__ wp) {
    int i = blockIdx.x * 256 + threadIdx.x;
    int which = i >> 16, j = i & 65535;
    const float* w = which == 0 ? wq : (which == 1 ? wk : (which == 2 ? wv : wp));
    g_w[i] = tf32r(w[j]);
}

__global__ void __launch_bounds__(256) gn_stats_kernel(const float* __restrict__ x) {
    int b = blockIdx.x >> 5, g = blockIdx.x & 31;
    const size_t base = ((size_t)b * C + g * 8) * NPOS;
    const float4* xp = (const float4*)(x + base);
    const int NV = 8 * NPOS / 4;
    float s = 0.f, ss = 0.f;
    for (int i = threadIdx.x; i < NV; i += 256) {
        float4 v = xp[i];
        s  += v.x + v.y + v.z + v.w;
        ss += v.x * v.x + v.y * v.y + v.z * v.z + v.w * v.w;
    }
    #pragma unroll
    for (int o = 16; o; o >>= 1) {
        s  += __shfl_xor_sync(0xffffffffu, s, o);
        ss += __shfl_xor_sync(0xffffffffu, ss, o);
    }
    __shared__ float shs[8], shss[8];
    int w = threadIdx.x >> 5;
    if ((threadIdx.x & 31) == 0) { shs[w] = s; shss[w] = ss; }
    __syncthreads();
    if (threadIdx.x == 0) {
        float ts = 0.f, tss = 0.f;
        #pragma unroll
        for (int i = 0; i < 8; ++i) { ts += shs[i]; tss += shss[i]; }
        const float invN = 1.f / (8 * NPOS);
        float mean = ts * invN;
        float var = tss * invN - mean * mean;
        g_stats[blockIdx.x * 2]     = mean;
        g_stats[blockIdx.x * 2 + 1] = rsqrtf(var + 1e-6f);
    }
}

__global__ void gn_apply_kernel(const float* __restrict__ x,
                                const float* __restrict__ gamma,
                                const float* __restrict__ beta) {
    __shared__ float tile[32][33];
    int b = blockIdx.z, c0b = blockIdx.y * 32, n0b = blockIdx.x * 32;
    int tx = threadIdx.x, ty = threadIdx.y;
    #pragma unroll
    for (int i = 0; i < 4; ++i) {
        int cl = ty + i * 8;
        int c = c0b + cl;
        int g = c >> 3;
        float mean = g_stats[(b * 32 + g) * 2];
        float inv  = g_stats[(b * 32 + g) * 2 + 1];
        float gmul = gamma[c] * inv;
        float gadd = beta[c] - mean * gmul;
        float v = x[((size_t)b * C + c) * NPOS + n0b + tx];
        tile[cl][tx] = v * gmul + gadd;
    }
    __syncthreads();
    #pragma unroll
    for (int i = 0; i < 4; ++i) {
        int nl = ty + i * 8;
        size_t o = ((size_t)b * NPOS + n0b + nl) * C + c0b + tx;
        g_h[o] = tf32r(tile[tx][nl]);
    }
}

// ---------------- GEMM kernels -----------------------------------------------
// Q/K: out[pos, cout] = H[pos,:] . W[cout,:]^T + bias
__global__ void __launch_bounds__(256, 2) qk_gemm(const float* __restrict__ bq,
                                                  const float* __restrict__ bk) {
    extern __shared__ char smem[];
    uint32_t sb = smem_u32(smem);
    int b = blockIdx.z >> 1, which = blockIdx.z & 1;
    int m0 = blockIdx.y * 128, n0 = blockIdx.x * 128;
    const float* A = g_h + ((size_t)b * NPOS + m0) * C;
    const float* B = g_w + (size_t)which * C * C + (size_t)n0 * C;
    float acc[4][4][4];
    gemm_run(sb, A, C, B, C, C, acc);

    const float* bias = which == 0 ? bq : bk;
    float* out = which == 0 ? g_q : g_k;
    EPI_COORDS;
    #pragma unroll
    for (int ni = 0; ni < 4; ++ni) {
        int colg = n0 + nw + ni * 8 + c0;
        float bb0 = bias[colg], bb1 = bias[colg + 1];
        #pragma unroll
        for (int mi = 0; mi < 4; ++mi)
            #pragma unroll
            for (int rr = 0; rr < 2; ++rr) {
                int rowg = m0 + mw + mi * 16 + r0 + rr * 8;
                size_t off = ((size_t)b * NPOS + rowg) * C + colg;
                float2 v = make_float2(tf32r(acc[mi][ni][rr * 2] + bb0),
                                       tf32r(acc[mi][ni][rr * 2 + 1] + bb1));
                *reinterpret_cast<float2*>(out + off) = v;
            }
    }
}

// V: out[c, pos] = Wv[c,:] . H[pos,:]^T + bv[c]   (channel-major)
__global__ void __launch_bounds__(256, 2) v_gemm(const float* __restrict__ bv) {
    extern __shared__ char smem[];
    uint32_t sb = smem_u32(smem);
    int b = blockIdx.z;
    int m0 = blockIdx.y * 128, n0 = blockIdx.x * 128;
    const float* A = g_w + (size_t)2 * C * C + (size_t)m0 * C;
    const float* B = g_h + ((size_t)b * NPOS + n0) * C;
    float acc[4][4][4];
    gemm_run(sb, A, C, B, C, C, acc);

    EPI_COORDS;
    #pragma unroll
    for (int mi = 0; mi < 4; ++mi)
        #pragma unroll
        for (int rr = 0; rr < 2; ++rr) {
            int rowg = m0 + mw + mi * 16 + r0 + rr * 8;
            float bb = bv[rowg];
            #pragma unroll
            for (int ni = 0; ni < 4; ++ni) {
                int colg = n0 + nw + ni * 8 + c0;
                size_t off = (size_t)b * CN + (size_t)rowg * NPOS + colg;
                float2 v = make_float2(tf32r(acc[mi][ni][rr * 2] + bb),
                                       tf32r(acc[mi][ni][rr * 2 + 1] + bb));
                *reinterpret_cast<float2*>(g_v + off) = v;
            }
        }
}

// S: [i,j] = 1/16 * Q[i,:] . K[j,:]^T
__global__ void __launch_bounds__(256, 2) s_gemm() {
    extern __shared__ char smem[];
    uint32_t sb = smem_u32(smem);
    int b = blockIdx.z;
    int m0 = blockIdx.y * 128, n0 = blockIdx.x * 128;
    const float* A = g_q + ((size_t)b * NPOS + m0) * C;
    const float* B = g_k + ((size_t)b * NPOS + n0) * C;
    float acc[4][4][4];
    gemm_run(sb, A, C, B, C, C, acc);

    EPI_COORDS;
    float* S = g_s + (size_t)b * SN;
    #pragma unroll
    for (int mi = 0; mi < 4; ++mi)
        #pragma unroll
        for (int rr = 0; rr < 2; ++rr) {
            int rowg = m0 + mw + mi * 16 + r0 + rr * 8;
            #pragma unroll
            for (int ni = 0; ni < 4; ++ni) {
                int colg = n0 + nw + ni * 8 + c0;
                float2 v = make_float2(acc[mi][ni][rr * 2] * 0.0625f,
                                       acc[mi][ni][rr * 2 + 1] * 0.0625f);
                *reinterpret_cast<float2*>(S + (size_t)rowg * NPOS + colg) = v;
            }
        }
}

// softmax rows of S -> P (tf32-rounded fp32, in place)
__global__ void __launch_bounds__(256) softmax_kernel() {
    size_t row = blockIdx.x;
    float* p = g_s + row * NPOS;
    const int tid = threadIdx.x;

    float4 r[4];
    #pragma unroll
    for (int c = 0; c < 4; ++c)
        r[c] = *(const float4*)(p + ((size_t)(tid + c * 256)) * 4);

    float m = -1e30f;
    #pragma unroll
    for (int c = 0; c < 4; ++c)
        m = fmaxf(m, fmaxf(fmaxf(r[c].x, r[c].y), fmaxf(r[c].z, r[c].w)));
    #pragma unroll
    for (int o = 16; o; o >>= 1) m = fmaxf(m, __shfl_xor_sync(0xffffffffu, m, o));
    __shared__ float shm[8], shsum[8];
    int w = tid >> 5;
    if ((tid & 31) == 0) shm[w] = m;
    __syncthreads();
    float mm = -1e30f;
    #pragma unroll
    for (int i = 0; i < 8; ++i) mm = fmaxf(mm, shm[i]);

    float s = 0.f;
    #pragma unroll
    for (int c = 0; c < 4; ++c) {
        r[c].x = expf(r[c].x - mm); r[c].y = expf(r[c].y - mm);
        r[c].z = expf(r[c].z - mm); r[c].w = expf(r[c].w - mm);
        s += r[c].x + r[c].y + r[c].z + r[c].w;
    }
    #pragma unroll
    for (int o = 16; o; o >>= 1) s += __shfl_xor_sync(0xffffffffu, s, o);
    if ((tid & 31) == 0) shsum[w] = s;
    __syncthreads();
    float ts = 0.f;
    #pragma unroll
    for (int i = 0; i < 8; ++i) ts += shsum[i];
    float inv = 1.f / ts;

    #pragma unroll
    for (int c = 0; c < 4; ++c) {
        float4 v = make_float4(tf32r(r[c].x * inv), tf32r(r[c].y * inv),
                               tf32r(r[c].z * inv), tf32r(r[c].w * inv));
        *(float4*)(p + ((size_t)(tid + c * 256)) * 4) = v;
    }
}

// AV: O[i, c] = P[i,:] . V[c,:]^T   (K = 4096), O position-major
__global__ void __launch_bounds__(256, 2) av_gemm() {
    extern __shared__ char smem[];
    uint32_t sb = smem_u32(smem);
    int b = blockIdx.z;
    int m0 = blockIdx.y * 128, n0 = blockIdx.x * 128;
    const float* A = g_s + (size_t)b * SN + (size_t)m0 * NPOS;
    const float* B = g_v + (size_t)b * CN + (size_t)n0 * NPOS;
    float acc[4][4][4];
    gemm_run(sb, A, NPOS, B, NPOS, NPOS, acc);

    EPI_COORDS;
    #pragma unroll
    for (int mi = 0; mi < 4; ++mi)
        #pragma unroll
        for (int rr = 0; rr < 2; ++rr) {
            int rowg = m0 + mw + mi * 16 + r0 + rr * 8;
            #pragma unroll
            for (int ni = 0; ni < 4; ++ni) {
                int colg = n0 + nw + ni * 8 + c0;
                size_t off = ((size_t)b * NPOS + rowg) * C + colg;
                float2 v = make_float2(tf32r(acc[mi][ni][rr * 2]),
                                       tf32r(acc[mi][ni][rr * 2 + 1]));
                *reinterpret_cast<float2*>(g_o + off) = v;
            }
        }
}

// proj: out[c, n] = x[c, n] + Wp[c,:] . O[n,:]^T + bp[c]
__global__ void __launch_bounds__(256, 2) proj_gemm(const float* __restrict__ bp,
                                                    const float* __restrict__ x,
                                                    float* __restrict__ out) {
    extern __shared__ char smem[];
    uint32_t sb = smem_u32(smem);
    int b = blockIdx.z;
    int m0 = blockIdx.y * 128, n0 = blockIdx.x * 128;
    const float* A = g_w + (size_t)3 * C * C + (size_t)m0 * C;
    const float* B = g_o + ((size_t)b * NPOS + n0) * C;
    float acc[4][4][4];
    gemm_run(sb, A, C, B, C, C, acc);

    EPI_COORDS;
    #pragma unroll
    for (int mi = 0; mi < 4; ++mi)
        #pragma unroll
        for (int rr = 0; rr < 2; ++rr) {
            int rowg = m0 + mw + mi * 16 + r0 + rr * 8;
            float bb = bp[rowg];
            #pragma unroll
            for (int ni = 0; ni < 4; ++ni) {
                int colg = n0 + nw + ni * 8 + c0;
                size_t off = (size_t)b * CN + (size_t)rowg * NPOS + colg;
                float2 xv = *reinterpret_cast<const float2*>(x + off);
                float2 ov = make_float2(xv.x + acc[mi][ni][rr * 2] + bb,
                                        xv.y + acc[mi][ni][rr * 2 + 1] + bb);
                *reinterpret_cast<float2*>(out + off) = ov;
            }
        }
}

// ---------------- launch ------------------------------------------------------
extern "C" void kernel_launch(void* const* d_in, const int* in_sizes, int n_in,
                              void* d_out, int out_size) {
    const float* x  = (const float*)d_in[0];
    const float* gs = (const float*)d_in[1];
    const float* gb = (const float*)d_in[2];
    const float* wq = (const float*)d_in[3];
    const float* bq = (const float*)d_in[4];
    const float* wk = (const float*)d_in[5];
    const float* bk = (const float*)d_in[6];
    const float* wv = (const float*)d_in[7];
    const float* bv = (const float*)d_in[8];
    const float* wp = (const float*)d_in[9];
    const float* bp = (const float*)d_in[10];
    float* out = (float*)d_out;

    static bool attr_done = false;
    if (!attr_done) {
        cudaFuncSetAttribute(qk_gemm,   cudaFuncAttributeMaxDynamicSharedMemorySize, SMEM_BYTES);
        cudaFuncSetAttribute(v_gemm,    cudaFuncAttributeMaxDynamicSharedMemorySize, SMEM_BYTES);
        cudaFuncSetAttribute(s_gemm,    cudaFuncAttributeMaxDynamicSharedMemorySize, SMEM_BYTES);
        cudaFuncSetAttribute(av_gemm,   cudaFuncAttributeMaxDynamicSharedMemorySize, SMEM_BYTES);
        cudaFuncSetAttribute(proj_gemm, cudaFuncAttributeMaxDynamicSharedMemorySize, SMEM_BYTES);
        attr_done = true;
    }

    conv_w_kernel<<<4 * C * C / 256, 256>>>(wq, wk, wv, wp);
    gn_stats_kernel<<<BATCH * 32, 256>>>(x);
    gn_apply_kernel<<<dim3(NPOS / 32, C / 32, BATCH), dim3(32, 8)>>>(x, gs, gb);
    qk_gemm<<<dim3(C / 128, NPOS / 128, 2 * BATCH), 256, SMEM_BYTES>>>(bq, bk);
    v_gemm<<<dim3(NPOS / 128, C / 128, BATCH), 256, SMEM_BYTES>>>(bv);
    s_gemm<<<dim3(NPOS / 128, NPOS / 128, BATCH), 256, SMEM_BYTES>>>();
    softmax_kernel<<<BATCH * NPOS, 256>>>();
    av_gemm<<<dim3(C / 128, NPOS / 128, BATCH), 256, SMEM_BYTES>>>();
    proj_gemm<<<dim3(NPOS / 128, C / 128, BATCH), 256, SMEM_BYTES>>>(bp, x, out);
}